// round 3
// baseline (speedup 1.0000x reference)
#include <cuda_runtime.h>
#include <math.h>

#define N_NODES 100000
#define N_EDGES 600000
#define N_GRAPH 2000
#define HDIM    128
#define N_LAYER 3
#define EPSV    1e-5f

// ---------------- scratch (device globals: no allocation allowed) ----------------
__device__ float    g_x[N_NODES * HDIM];        // node state
__device__ float    g_PQ[N_NODES * 512];        // [P(256) | Q(256)] per node
__device__ float    g_Hagg[N_NODES * 256];      // segment-summed hidden
__device__ float    g_aggr[N_NODES * HDIM];     // aggr = Hagg@W2 + deg*b2
__device__ float    g_gi[N_NODES * 384];
__device__ float    g_gh[N_NODES * 384];
__device__ int      g_deg[N_NODES];
__device__ float    g_degf[N_NODES];
__device__ int      g_rowstart[N_NODES + 1];
__device__ int      g_cursor[N_NODES];
__device__ int      g_eid[N_EDGES];
__device__ float    g_pool_sum[N_GRAPH * HDIM];
__device__ unsigned g_pool_max[N_GRAPH * HDIM];
__device__ int      g_cnt[N_GRAPH];

// ---------------- helpers ----------------
__device__ __forceinline__ float wsum(float v) {
#pragma unroll
    for (int o = 16; o > 0; o >>= 1) v += __shfl_xor_sync(0xffffffffu, v, o);
    return v;
}

__device__ __forceinline__ unsigned fenc(float x) {
    unsigned u = __float_as_uint(x);
    return (u & 0x80000000u) ? ~u : (u | 0x80000000u);
}
__device__ __forceinline__ float fdec(unsigned k) {
    unsigned u = (k & 0x80000000u) ? (k & 0x7fffffffu) : ~k;
    return __uint_as_float(u);
}

// ---------------- encoder: x = LN(relu(af @ enc_w + enc_b)) ----------------
__global__ void encoder_k(const float* __restrict__ af, const float* __restrict__ w,
                          const float* __restrict__ b, const float* __restrict__ lg,
                          const float* __restrict__ lb) {
    int idx = blockIdx.x * blockDim.x + threadIdx.x;
    int n = idx >> 5, lane = idx & 31;
    if (n >= N_NODES) return;
    float a0 = af[n * 4 + 0], a1 = af[n * 4 + 1], a2 = af[n * 4 + 2], a3 = af[n * 4 + 3];
    float t[4];
    float s = 0.f;
#pragma unroll
    for (int i = 0; i < 4; i++) {
        int c = lane + 32 * i;
        float v = a0 * w[c] + a1 * w[128 + c] + a2 * w[256 + c] + a3 * w[384 + c] + b[c];
        t[i] = fmaxf(v, 0.f);
        s += t[i];
    }
    float m = wsum(s) * (1.f / 128.f);
    float var = 0.f;
#pragma unroll
    for (int i = 0; i < 4; i++) { float d = t[i] - m; var += d * d; }
    var = wsum(var) * (1.f / 128.f);
    float inv = rsqrtf(var + EPSV);
#pragma unroll
    for (int i = 0; i < 4; i++) {
        int c = lane + 32 * i;
        g_x[n * HDIM + c] = (t[i] - m) * inv * lg[c] + lb[c];
    }
}

// ---------------- CSR build ----------------
__global__ void deg_k(const int* __restrict__ ei) {
    int e = blockIdx.x * blockDim.x + threadIdx.x;
    if (e >= N_EDGES) return;
    atomicAdd(&g_deg[ei[N_EDGES + e]], 1);
}

__global__ void scan_k() {
    __shared__ int sh[1024];
    __shared__ int carry;
    int t = threadIdx.x;
    if (t == 0) carry = 0;
    __syncthreads();
    for (int base = 0; base < N_NODES; base += 1024) {
        int i = base + t;
        int v = (i < N_NODES) ? g_deg[i] : 0;
        sh[t] = v;
        __syncthreads();
        for (int off = 1; off < 1024; off <<= 1) {
            int add = (t >= off) ? sh[t - off] : 0;
            __syncthreads();
            sh[t] += add;
            __syncthreads();
        }
        int excl = sh[t] - v;
        if (i < N_NODES) {
            int rs = carry + excl;
            g_rowstart[i] = rs;
            g_cursor[i] = rs;
            g_degf[i] = (float)v;
        }
        __syncthreads();
        if (t == 1023) carry += sh[1023];
        __syncthreads();
    }
    if (t == 0) g_rowstart[N_NODES] = carry;
}

__global__ void scatter_k(const int* __restrict__ ei) {
    int e = blockIdx.x * blockDim.x + threadIdx.x;
    if (e >= N_EDGES) return;
    int pos = atomicAdd(&g_cursor[ei[N_EDGES + e]], 1);
    g_eid[pos] = e;
}

// ---------------- SGEMM: C[M,Nc] = A[M,K] @ op(B) (+bias +rs*rv) ----------------
// TB=false: B row-major [K,Nc] (ldb = row stride)
// TB=true : B row-major [Nc,K], effective B^T (ldb = row stride of B)
template <bool TB>
__global__ __launch_bounds__(256) void sgemm_k(
    const float* __restrict__ A, const float* __restrict__ B, float* __restrict__ C,
    int M, int K, int Nc, int lda, int ldb, int ldc,
    const float* __restrict__ bias, const float* __restrict__ rs,
    const float* __restrict__ rv) {
    const int BM = 128, BN = 64, BK = 16;
    __shared__ float As[BK][BM + 4];
    __shared__ float Bs[BK][BN + 4];
    int tid = threadIdx.x;
    int tx = tid & 15, ty = tid >> 4;
    int m0 = blockIdx.x * BM;
    int n0 = blockIdx.y * BN;
    float acc[8][4];
#pragma unroll
    for (int i = 0; i < 8; i++)
#pragma unroll
        for (int j = 0; j < 4; j++) acc[i][j] = 0.f;

    for (int k0 = 0; k0 < K; k0 += BK) {
#pragma unroll
        for (int r = 0; r < 2; r++) {
            int f4 = tid + 256 * r;
            int m = f4 >> 2;
            int kq = (f4 & 3) * 4;
            float4 v = make_float4(0.f, 0.f, 0.f, 0.f);
            if (m0 + m < M)
                v = *(const float4*)(A + (size_t)(m0 + m) * lda + k0 + kq);
            As[kq + 0][m] = v.x; As[kq + 1][m] = v.y;
            As[kq + 2][m] = v.z; As[kq + 3][m] = v.w;
        }
        if (!TB) {
            int kb = tid >> 4;
            int c4 = (tid & 15) * 4;
            float4 v = *(const float4*)(B + (size_t)(k0 + kb) * ldb + n0 + c4);
            *(float4*)&Bs[kb][c4] = v;
        } else {
            int nn_ = tid >> 2;
            int kq = (tid & 3) * 4;
            float4 v = *(const float4*)(B + (size_t)(n0 + nn_) * ldb + k0 + kq);
            Bs[kq + 0][nn_] = v.x; Bs[kq + 1][nn_] = v.y;
            Bs[kq + 2][nn_] = v.z; Bs[kq + 3][nn_] = v.w;
        }
        __syncthreads();
#pragma unroll
        for (int kk = 0; kk < BK; kk++) {
            float4 a0 = *(const float4*)&As[kk][ty * 8];
            float4 a1 = *(const float4*)&As[kk][ty * 8 + 4];
            float4 bv = *(const float4*)&Bs[kk][tx * 4];
            float ar[8] = {a0.x, a0.y, a0.z, a0.w, a1.x, a1.y, a1.z, a1.w};
            float br[4] = {bv.x, bv.y, bv.z, bv.w};
#pragma unroll
            for (int i = 0; i < 8; i++)
#pragma unroll
                for (int j = 0; j < 4; j++) acc[i][j] += ar[i] * br[j];
        }
        __syncthreads();
    }
    int c = n0 + tx * 4;
    float b0 = 0.f, b1 = 0.f, b2 = 0.f, b3 = 0.f;
    if (bias) { b0 = bias[c]; b1 = bias[c + 1]; b2 = bias[c + 2]; b3 = bias[c + 3]; }
    float v0 = 0.f, v1 = 0.f, v2 = 0.f, v3 = 0.f;
    if (rv) { v0 = rv[c]; v1 = rv[c + 1]; v2 = rv[c + 2]; v3 = rv[c + 3]; }
#pragma unroll
    for (int i = 0; i < 8; i++) {
        int m = m0 + ty * 8 + i;
        if (m < M) {
            float rsm = rs ? rs[m] : 0.f;
            float4 o;
            o.x = acc[i][0] + b0 + rsm * v0;
            o.y = acc[i][1] + b1 + rsm * v1;
            o.z = acc[i][2] + b2 + rsm * v2;
            o.w = acc[i][3] + b3 + rsm * v3;
            *(float4*)(C + (size_t)m * ldc + c) = o;
        }
    }
}

// ---------------- edge aggregation: Hagg[n] = sum_{e:dst=n} relu(P[src]+Q[n]+ea*w1c+b1) ----------------
__global__ void edge_agg_k(const int* __restrict__ ei, const float* __restrict__ ea,
                           const float* __restrict__ w1c, const float* __restrict__ b1) {
    int idx = blockIdx.x * blockDim.x + threadIdx.x;
    int n = idx >> 5, lane = idx & 31;
    if (n >= N_NODES) return;
    const float4* PQ4 = (const float4*)g_PQ;
    float4 q0 = PQ4[n * 128 + 64 + lane];
    float4 q1 = PQ4[n * 128 + 96 + lane];
    float4 wc0 = ((const float4*)w1c)[lane];
    float4 wc1 = ((const float4*)w1c)[lane + 32];
    float4 bb0 = ((const float4*)b1)[lane];
    float4 bb1 = ((const float4*)b1)[lane + 32];
    float4 acc0 = make_float4(0.f, 0.f, 0.f, 0.f);
    float4 acc1 = make_float4(0.f, 0.f, 0.f, 0.f);
    int s0 = g_rowstart[n], s1 = g_rowstart[n + 1];
    for (int i = s0; i < s1; i++) {
        int e = g_eid[i];
        int src = ei[e];
        float a = ea[e];
        float4 p0 = PQ4[src * 128 + lane];
        float4 p1 = PQ4[src * 128 + 32 + lane];
        acc0.x += fmaxf(p0.x + q0.x + a * wc0.x + bb0.x, 0.f);
        acc0.y += fmaxf(p0.y + q0.y + a * wc0.y + bb0.y, 0.f);
        acc0.z += fmaxf(p0.z + q0.z + a * wc0.z + bb0.z, 0.f);
        acc0.w += fmaxf(p0.w + q0.w + a * wc0.w + bb0.w, 0.f);
        acc1.x += fmaxf(p1.x + q1.x + a * wc1.x + bb1.x, 0.f);
        acc1.y += fmaxf(p1.y + q1.y + a * wc1.y + bb1.y, 0.f);
        acc1.z += fmaxf(p1.z + q1.z + a * wc1.z + bb1.z, 0.f);
        acc1.w += fmaxf(p1.w + q1.w + a * wc1.w + bb1.w, 0.f);
    }
    ((float4*)g_Hagg)[n * 64 + lane] = acc0;
    ((float4*)g_Hagg)[n * 64 + 32 + lane] = acc1;
}

// ---------------- GRU + LN: x = LN(x + GRU(aggr, x)) ----------------
__global__ void gru_ln_k(const float* __restrict__ lg, const float* __restrict__ lb) {
    int idx = blockIdx.x * blockDim.x + threadIdx.x;
    int n = idx >> 5, lane = idx & 31;
    if (n >= N_NODES) return;
    float pre[4];
    float s = 0.f;
#pragma unroll
    for (int i = 0; i < 4; i++) {
        int c = lane + 32 * i;
        float ir = g_gi[n * 384 + c];
        float iz = g_gi[n * 384 + 128 + c];
        float inn = g_gi[n * 384 + 256 + c];
        float hr = g_gh[n * 384 + c];
        float hz = g_gh[n * 384 + 128 + c];
        float hn = g_gh[n * 384 + 256 + c];
        float xo = g_x[n * HDIM + c];
        float r = 1.f / (1.f + expf(-(ir + hr)));
        float z = 1.f / (1.f + expf(-(iz + hz)));
        float nv = tanhf(inn + r * hn);
        float xn = (1.f - z) * nv + z * xo;
        pre[i] = xo + xn;
        s += pre[i];
    }
    float m = wsum(s) * (1.f / 128.f);
    float var = 0.f;
#pragma unroll
    for (int i = 0; i < 4; i++) { float d = pre[i] - m; var += d * d; }
    var = wsum(var) * (1.f / 128.f);
    float inv = rsqrtf(var + EPSV);
#pragma unroll
    for (int i = 0; i < 4; i++) {
        int c = lane + 32 * i;
        g_x[n * HDIM + c] = (pre[i] - m) * inv * lg[c] + lb[c];
    }
}

// ---------------- pooling ----------------
__global__ void init_pool_k() {
    int i = blockIdx.x * blockDim.x + threadIdx.x;
    if (i < N_GRAPH * HDIM) {
        g_pool_sum[i] = 0.f;
        g_pool_max[i] = 0x00800000u;  // fenc(-FLT_MAX)
    }
    if (i < N_GRAPH) g_cnt[i] = 0;
}

__global__ void cnt_k(const int* __restrict__ batch) {
    int n = blockIdx.x * blockDim.x + threadIdx.x;
    if (n >= N_NODES) return;
    atomicAdd(&g_cnt[batch[n]], 1);
}

__global__ void pool_k(const int* __restrict__ batch) {
    int i = blockIdx.x * blockDim.x + threadIdx.x;
    if (i >= N_NODES * HDIM) return;
    int n = i >> 7, c = i & 127;
    int g = batch[n];
    float v = g_x[i];
    atomicAdd(&g_pool_sum[g * HDIM + c], v);
    atomicMax(&g_pool_max[g * HDIM + c], fenc(v));
}

// ---------------- readout MLP ----------------
__global__ void readout_k(const float* __restrict__ w1, const float* __restrict__ b1,
                          const float* __restrict__ w2, const float* __restrict__ b2,
                          const float* __restrict__ w3, const float* __restrict__ b3,
                          float* __restrict__ out) {
    int g = blockIdx.x;
    int t = threadIdx.x;  // 128
    __shared__ float gv[256];
    __shared__ float h1[128];
    __shared__ float h2[64];
    float cn = fmaxf((float)g_cnt[g], 1.f);
    gv[t] = g_pool_sum[g * HDIM + t] / cn;
    gv[128 + t] = fdec(g_pool_max[g * HDIM + t]);
    __syncthreads();
    float a = 0.f;
    for (int i = 0; i < 256; i++) a += gv[i] * w1[i * 128 + t];
    h1[t] = fmaxf(a + b1[t], 0.f);
    __syncthreads();
    if (t < 64) {
        a = 0.f;
        for (int i = 0; i < 128; i++) a += h1[i] * w2[i * 64 + t];
        h2[t] = fmaxf(a + b2[t], 0.f);
    }
    __syncthreads();
    if (t < 113) {
        a = 0.f;
        for (int i = 0; i < 64; i++) a += h2[i] * w3[i * 113 + t];
        out[g * 113 + t] = a + b3[t];
    }
}

// ---------------- launch ----------------
extern "C" void kernel_launch(void* const* d_in, const int* in_sizes, int n_in,
                              void* d_out, int out_size) {
    const float* af     = (const float*)d_in[0];
    const int*   ei     = (const int*)d_in[1];
    const float* ea     = (const float*)d_in[2];
    const int*   batch  = (const int*)d_in[3];
    const float* enc_w  = (const float*)d_in[4];
    const float* enc_b  = (const float*)d_in[5];
    const float* enc_g  = (const float*)d_in[6];
    const float* enc_bb = (const float*)d_in[7];
    const float* msg_w1 = (const float*)d_in[8];
    const float* msg_b1 = (const float*)d_in[9];
    const float* msg_w2 = (const float*)d_in[10];
    const float* msg_b2 = (const float*)d_in[11];
    const float* wih    = (const float*)d_in[12];
    const float* whh    = (const float*)d_in[13];
    const float* bih    = (const float*)d_in[14];
    const float* bhh    = (const float*)d_in[15];
    const float* ln_g   = (const float*)d_in[16];
    const float* ln_b   = (const float*)d_in[17];
    const float* ro_w1  = (const float*)d_in[18];
    const float* ro_b1  = (const float*)d_in[19];
    const float* ro_w2  = (const float*)d_in[20];
    const float* ro_b2  = (const float*)d_in[21];
    const float* ro_w3  = (const float*)d_in[22];
    const float* ro_b3  = (const float*)d_in[23];
    float* out = (float*)d_out;

    float *px, *pPQ, *pH, *pA, *pgi, *pgh, *pdegf;
    int* pdeg;
    cudaGetSymbolAddress((void**)&px, g_x);
    cudaGetSymbolAddress((void**)&pPQ, g_PQ);
    cudaGetSymbolAddress((void**)&pH, g_Hagg);
    cudaGetSymbolAddress((void**)&pA, g_aggr);
    cudaGetSymbolAddress((void**)&pgi, g_gi);
    cudaGetSymbolAddress((void**)&pgh, g_gh);
    cudaGetSymbolAddress((void**)&pdegf, g_degf);
    cudaGetSymbolAddress((void**)&pdeg, g_deg);

    cudaMemsetAsync(pdeg, 0, N_NODES * sizeof(int));

    encoder_k<<<(N_NODES + 7) / 8, 256>>>(af, enc_w, enc_b, enc_g, enc_bb);
    deg_k<<<(N_EDGES + 255) / 256, 256>>>(ei);
    scan_k<<<1, 1024>>>();
    scatter_k<<<(N_EDGES + 255) / 256, 256>>>(ei);

    const int MB = (N_NODES + 127) / 128;  // 782
    for (int l = 0; l < N_LAYER; l++) {
        const float* w1   = msg_w1 + (size_t)l * 257 * 256;
        const float* b1   = msg_b1 + (size_t)l * 256;
        const float* w2   = msg_w2 + (size_t)l * 256 * 128;
        const float* b2   = msg_b2 + (size_t)l * 128;
        const float* wihl = wih + (size_t)l * 384 * 128;
        const float* whhl = whh + (size_t)l * 384 * 128;
        const float* bihl = bih + (size_t)l * 384;
        const float* bhhl = bhh + (size_t)l * 384;

        dim3 gPQ(MB, 4);
        sgemm_k<false><<<gPQ, 256>>>(px, w1, pPQ, N_NODES, 128, 256, 128, 256, 512,
                                     nullptr, nullptr, nullptr);
        sgemm_k<false><<<gPQ, 256>>>(px, w1 + 128 * 256, pPQ + 256, N_NODES, 128, 256,
                                     128, 256, 512, nullptr, nullptr, nullptr);

        edge_agg_k<<<(N_NODES * 32 + 255) / 256, 256>>>(ei, ea, w1 + 256 * 256, b1);

        dim3 gAG(MB, 2);
        sgemm_k<false><<<gAG, 256>>>(pH, w2, pA, N_NODES, 256, 128, 256, 128, 128,
                                     nullptr, pdegf, b2);

        dim3 gGR(MB, 6);
        sgemm_k<true><<<gGR, 256>>>(pA, wihl, pgi, N_NODES, 128, 384, 128, 128, 384,
                                    bihl, nullptr, nullptr);
        sgemm_k<true><<<gGR, 256>>>(px, whhl, pgh, N_NODES, 128, 384, 128, 128, 384,
                                    bhhl, nullptr, nullptr);

        gru_ln_k<<<(N_NODES * 32 + 255) / 256, 256>>>(ln_g + (size_t)l * 128,
                                                      ln_b + (size_t)l * 128);
    }

    init_pool_k<<<(N_GRAPH * HDIM + 255) / 256, 256>>>();
    cnt_k<<<(N_NODES + 255) / 256, 256>>>(batch);
    pool_k<<<(N_NODES * HDIM + 255) / 256, 256>>>(batch);
    readout_k<<<N_GRAPH, 128>>>(ro_w1, ro_b1, ro_w2, ro_b2, ro_w3, ro_b3, out);
}

// round 4
// speedup vs baseline: 1.0037x; 1.0037x over previous
#include <cuda_runtime.h>
#include <math.h>

#define N_NODES 100000
#define N_EDGES 600000
#define N_GRAPH 2000
#define HDIM    128
#define N_LAYER 3
#define EPSV    1e-5f

// ---------------- scratch (device globals: no allocation allowed) ----------------
__device__ float    g_x[N_NODES * HDIM];        // node state
__device__ float    g_PQ[N_NODES * 512];        // [P(256) | Q(256)] per node
__device__ float    g_Hagg[N_NODES * 256];      // segment-summed hidden
__device__ float    g_aggr[N_NODES * HDIM];     // aggr = Hagg@W2 + deg*b2
__device__ float    g_gi[N_NODES * 384];
__device__ float    g_gh[N_NODES * 384];
__device__ int      g_deg[N_NODES];
__device__ float    g_degf[N_NODES];
__device__ int      g_rowstart[N_NODES + 1];
__device__ int      g_cursor[N_NODES];
__device__ int      g_eid[N_EDGES];
__device__ float    g_pool_sum[N_GRAPH * HDIM];
__device__ unsigned g_pool_max[N_GRAPH * HDIM];
__device__ int      g_cnt[N_GRAPH];

// ---------------- helpers ----------------
__device__ __forceinline__ float wsum(float v) {
#pragma unroll
    for (int o = 16; o > 0; o >>= 1) v += __shfl_xor_sync(0xffffffffu, v, o);
    return v;
}

__device__ __forceinline__ unsigned fenc(float x) {
    unsigned u = __float_as_uint(x);
    return (u & 0x80000000u) ? ~u : (u | 0x80000000u);
}
__device__ __forceinline__ float fdec(unsigned k) {
    unsigned u = (k & 0x80000000u) ? (k & 0x7fffffffu) : ~k;
    return __uint_as_float(u);
}

// ---------------- encoder: x = LN(relu(af @ enc_w + enc_b)) ----------------
__global__ void encoder_k(const float* __restrict__ af, const float* __restrict__ w,
                          const float* __restrict__ b, const float* __restrict__ lg,
                          const float* __restrict__ lb) {
    int idx = blockIdx.x * blockDim.x + threadIdx.x;
    int n = idx >> 5, lane = idx & 31;
    if (n >= N_NODES) return;
    float a0 = af[n * 4 + 0], a1 = af[n * 4 + 1], a2 = af[n * 4 + 2], a3 = af[n * 4 + 3];
    float t[4];
    float s = 0.f;
#pragma unroll
    for (int i = 0; i < 4; i++) {
        int c = lane + 32 * i;
        float v = a0 * w[c] + a1 * w[128 + c] + a2 * w[256 + c] + a3 * w[384 + c] + b[c];
        t[i] = fmaxf(v, 0.f);
        s += t[i];
    }
    float m = wsum(s) * (1.f / 128.f);
    float var = 0.f;
#pragma unroll
    for (int i = 0; i < 4; i++) { float d = t[i] - m; var += d * d; }
    var = wsum(var) * (1.f / 128.f);
    float inv = rsqrtf(var + EPSV);
#pragma unroll
    for (int i = 0; i < 4; i++) {
        int c = lane + 32 * i;
        g_x[n * HDIM + c] = (t[i] - m) * inv * lg[c] + lb[c];
    }
}

// ---------------- CSR build ----------------
__global__ void deg_k(const int* __restrict__ ei) {
    int e = blockIdx.x * blockDim.x + threadIdx.x;
    if (e >= N_EDGES) return;
    atomicAdd(&g_deg[ei[N_EDGES + e]], 1);
}

__global__ void scan_k() {
    __shared__ int sh[1024];
    __shared__ int carry;
    int t = threadIdx.x;
    if (t == 0) carry = 0;
    __syncthreads();
    for (int base = 0; base < N_NODES; base += 1024) {
        int i = base + t;
        int v = (i < N_NODES) ? g_deg[i] : 0;
        sh[t] = v;
        __syncthreads();
        for (int off = 1; off < 1024; off <<= 1) {
            int add = (t >= off) ? sh[t - off] : 0;
            __syncthreads();
            sh[t] += add;
            __syncthreads();
        }
        int excl = sh[t] - v;
        if (i < N_NODES) {
            int rs = carry + excl;
            g_rowstart[i] = rs;
            g_cursor[i] = rs;
            g_degf[i] = (float)v;
        }
        __syncthreads();
        if (t == 1023) carry += sh[1023];
        __syncthreads();
    }
    if (t == 0) g_rowstart[N_NODES] = carry;
}

__global__ void scatter_k(const int* __restrict__ ei) {
    int e = blockIdx.x * blockDim.x + threadIdx.x;
    if (e >= N_EDGES) return;
    int pos = atomicAdd(&g_cursor[ei[N_EDGES + e]], 1);
    g_eid[pos] = e;
}

// ---------------- SGEMM: C[M,Nc] = A[M,K] @ op(B) (+bias +rs*rv) ----------------
// TB=false: B row-major [K,Nc] (ldb = row stride)
// TB=true : B row-major [Nc,K], effective B^T (ldb = row stride of B)
template <bool TB>
__global__ __launch_bounds__(256) void sgemm_k(
    const float* __restrict__ A, const float* __restrict__ B, float* __restrict__ C,
    int M, int K, int Nc, int lda, int ldb, int ldc,
    const float* __restrict__ bias, const float* __restrict__ rs,
    const float* __restrict__ rv) {
    const int BM = 128, BN = 64, BK = 16;
    __shared__ float As[BK][BM + 4];
    __shared__ float Bs[BK][BN + 4];
    int tid = threadIdx.x;
    int tx = tid & 15, ty = tid >> 4;
    int m0 = blockIdx.x * BM;
    int n0 = blockIdx.y * BN;
    float acc[8][4];
#pragma unroll
    for (int i = 0; i < 8; i++)
#pragma unroll
        for (int j = 0; j < 4; j++) acc[i][j] = 0.f;

    for (int k0 = 0; k0 < K; k0 += BK) {
#pragma unroll
        for (int r = 0; r < 2; r++) {
            int f4 = tid + 256 * r;
            int m = f4 >> 2;
            int kq = (f4 & 3) * 4;
            float4 v = make_float4(0.f, 0.f, 0.f, 0.f);
            if (m0 + m < M)
                v = *(const float4*)(A + (size_t)(m0 + m) * lda + k0 + kq);
            As[kq + 0][m] = v.x; As[kq + 1][m] = v.y;
            As[kq + 2][m] = v.z; As[kq + 3][m] = v.w;
        }
        if (!TB) {
            int kb = tid >> 4;
            int c4 = (tid & 15) * 4;
            float4 v = *(const float4*)(B + (size_t)(k0 + kb) * ldb + n0 + c4);
            *(float4*)&Bs[kb][c4] = v;
        } else {
            int nn_ = tid >> 2;
            int kq = (tid & 3) * 4;
            float4 v = *(const float4*)(B + (size_t)(n0 + nn_) * ldb + k0 + kq);
            Bs[kq + 0][nn_] = v.x; Bs[kq + 1][nn_] = v.y;
            Bs[kq + 2][nn_] = v.z; Bs[kq + 3][nn_] = v.w;
        }
        __syncthreads();
#pragma unroll
        for (int kk = 0; kk < BK; kk++) {
            float4 a0 = *(const float4*)&As[kk][ty * 8];
            float4 a1 = *(const float4*)&As[kk][ty * 8 + 4];
            float4 bv = *(const float4*)&Bs[kk][tx * 4];
            float ar[8] = {a0.x, a0.y, a0.z, a0.w, a1.x, a1.y, a1.z, a1.w};
            float br[4] = {bv.x, bv.y, bv.z, bv.w};
#pragma unroll
            for (int i = 0; i < 8; i++)
#pragma unroll
                for (int j = 0; j < 4; j++) acc[i][j] += ar[i] * br[j];
        }
        __syncthreads();
    }
    int c = n0 + tx * 4;
    float b0 = 0.f, b1 = 0.f, b2 = 0.f, b3 = 0.f;
    if (bias) { b0 = bias[c]; b1 = bias[c + 1]; b2 = bias[c + 2]; b3 = bias[c + 3]; }
    float v0 = 0.f, v1 = 0.f, v2 = 0.f, v3 = 0.f;
    if (rv) { v0 = rv[c]; v1 = rv[c + 1]; v2 = rv[c + 2]; v3 = rv[c + 3]; }
#pragma unroll
    for (int i = 0; i < 8; i++) {
        int m = m0 + ty * 8 + i;
        if (m < M) {
            float rsm = rs ? rs[m] : 0.f;
            float4 o;
            o.x = acc[i][0] + b0 + rsm * v0;
            o.y = acc[i][1] + b1 + rsm * v1;
            o.z = acc[i][2] + b2 + rsm * v2;
            o.w = acc[i][3] + b3 + rsm * v3;
            *(float4*)(C + (size_t)m * ldc + c) = o;
        }
    }
}

// ---------------- edge aggregation: Hagg[n] = sum_{e:dst=n} relu(P[src]+Q[n]+ea*w1c+b1) ----------------
__global__ void edge_agg_k(const int* __restrict__ ei, const float* __restrict__ ea,
                           const float* __restrict__ w1c, const float* __restrict__ b1) {
    int idx = blockIdx.x * blockDim.x + threadIdx.x;
    int n = idx >> 5, lane = idx & 31;
    if (n >= N_NODES) return;
    const float4* PQ4 = (const float4*)g_PQ;
    float4 q0 = PQ4[n * 128 + 64 + lane];
    float4 q1 = PQ4[n * 128 + 96 + lane];
    float4 wc0 = ((const float4*)w1c)[lane];
    float4 wc1 = ((const float4*)w1c)[lane + 32];
    float4 bb0 = ((const float4*)b1)[lane];
    float4 bb1 = ((const float4*)b1)[lane + 32];
    float4 acc0 = make_float4(0.f, 0.f, 0.f, 0.f);
    float4 acc1 = make_float4(0.f, 0.f, 0.f, 0.f);
    int s0 = g_rowstart[n], s1 = g_rowstart[n + 1];
    for (int i = s0; i < s1; i++) {
        int e = g_eid[i];
        int src = ei[e];
        float a = ea[e];
        float4 p0 = PQ4[src * 128 + lane];
        float4 p1 = PQ4[src * 128 + 32 + lane];
        acc0.x += fmaxf(p0.x + q0.x + a * wc0.x + bb0.x, 0.f);
        acc0.y += fmaxf(p0.y + q0.y + a * wc0.y + bb0.y, 0.f);
        acc0.z += fmaxf(p0.z + q0.z + a * wc0.z + bb0.z, 0.f);
        acc0.w += fmaxf(p0.w + q0.w + a * wc0.w + bb0.w, 0.f);
        acc1.x += fmaxf(p1.x + q1.x + a * wc1.x + bb1.x, 0.f);
        acc1.y += fmaxf(p1.y + q1.y + a * wc1.y + bb1.y, 0.f);
        acc1.z += fmaxf(p1.z + q1.z + a * wc1.z + bb1.z, 0.f);
        acc1.w += fmaxf(p1.w + q1.w + a * wc1.w + bb1.w, 0.f);
    }
    ((float4*)g_Hagg)[n * 64 + lane] = acc0;
    ((float4*)g_Hagg)[n * 64 + 32 + lane] = acc1;
}

// ---------------- GRU + LN: x = LN(x + GRU(aggr, x)) ----------------
__global__ void gru_ln_k(const float* __restrict__ lg, const float* __restrict__ lb) {
    int idx = blockIdx.x * blockDim.x + threadIdx.x;
    int n = idx >> 5, lane = idx & 31;
    if (n >= N_NODES) return;
    float pre[4];
    float s = 0.f;
#pragma unroll
    for (int i = 0; i < 4; i++) {
        int c = lane + 32 * i;
        float ir = g_gi[n * 384 + c];
        float iz = g_gi[n * 384 + 128 + c];
        float inn = g_gi[n * 384 + 256 + c];
        float hr = g_gh[n * 384 + c];
        float hz = g_gh[n * 384 + 128 + c];
        float hn = g_gh[n * 384 + 256 + c];
        float xo = g_x[n * HDIM + c];
        float r = 1.f / (1.f + expf(-(ir + hr)));
        float z = 1.f / (1.f + expf(-(iz + hz)));
        float nv = tanhf(inn + r * hn);
        float xn = (1.f - z) * nv + z * xo;
        pre[i] = xo + xn;
        s += pre[i];
    }
    float m = wsum(s) * (1.f / 128.f);
    float var = 0.f;
#pragma unroll
    for (int i = 0; i < 4; i++) { float d = pre[i] - m; var += d * d; }
    var = wsum(var) * (1.f / 128.f);
    float inv = rsqrtf(var + EPSV);
#pragma unroll
    for (int i = 0; i < 4; i++) {
        int c = lane + 32 * i;
        g_x[n * HDIM + c] = (pre[i] - m) * inv * lg[c] + lb[c];
    }
}

// ---------------- pooling ----------------
__global__ void init_pool_k() {
    int i = blockIdx.x * blockDim.x + threadIdx.x;
    if (i < N_GRAPH * HDIM) {
        g_pool_sum[i] = 0.f;
        g_pool_max[i] = 0x00800000u;  // fenc(-FLT_MAX)
    }
    if (i < N_GRAPH) g_cnt[i] = 0;
}

__global__ void cnt_k(const int* __restrict__ batch) {
    int n = blockIdx.x * blockDim.x + threadIdx.x;
    if (n >= N_NODES) return;
    atomicAdd(&g_cnt[batch[n]], 1);
}

__global__ void pool_k(const int* __restrict__ batch) {
    int i = blockIdx.x * blockDim.x + threadIdx.x;
    if (i >= N_NODES * HDIM) return;
    int n = i >> 7, c = i & 127;
    int g = batch[n];
    float v = g_x[i];
    atomicAdd(&g_pool_sum[g * HDIM + c], v);
    atomicMax(&g_pool_max[g * HDIM + c], fenc(v));
}

// ---------------- readout MLP ----------------
__global__ void readout_k(const float* __restrict__ w1, const float* __restrict__ b1,
                          const float* __restrict__ w2, const float* __restrict__ b2,
                          const float* __restrict__ w3, const float* __restrict__ b3,
                          float* __restrict__ out) {
    int g = blockIdx.x;
    int t = threadIdx.x;  // 128
    __shared__ float gv[256];
    __shared__ float h1[128];
    __shared__ float h2[64];
    float cn = fmaxf((float)g_cnt[g], 1.f);
    gv[t] = g_pool_sum[g * HDIM + t] / cn;
    gv[128 + t] = fdec(g_pool_max[g * HDIM + t]);
    __syncthreads();
    float a = 0.f;
    for (int i = 0; i < 256; i++) a += gv[i] * w1[i * 128 + t];
    h1[t] = fmaxf(a + b1[t], 0.f);
    __syncthreads();
    if (t < 64) {
        a = 0.f;
        for (int i = 0; i < 128; i++) a += h1[i] * w2[i * 64 + t];
        h2[t] = fmaxf(a + b2[t], 0.f);
    }
    __syncthreads();
    if (t < 113) {
        a = 0.f;
        for (int i = 0; i < 64; i++) a += h2[i] * w3[i * 113 + t];
        out[g * 113 + t] = a + b3[t];
    }
}

// ---------------- launch ----------------
extern "C" void kernel_launch(void* const* d_in, const int* in_sizes, int n_in,
                              void* d_out, int out_size) {
    const float* af     = (const float*)d_in[0];
    const int*   ei     = (const int*)d_in[1];
    const float* ea     = (const float*)d_in[2];
    const int*   batch  = (const int*)d_in[3];
    const float* enc_w  = (const float*)d_in[4];
    const float* enc_b  = (const float*)d_in[5];
    const float* enc_g  = (const float*)d_in[6];
    const float* enc_bb = (const float*)d_in[7];
    const float* msg_w1 = (const float*)d_in[8];
    const float* msg_b1 = (const float*)d_in[9];
    const float* msg_w2 = (const float*)d_in[10];
    const float* msg_b2 = (const float*)d_in[11];
    const float* wih    = (const float*)d_in[12];
    const float* whh    = (const float*)d_in[13];
    const float* bih    = (const float*)d_in[14];
    const float* bhh    = (const float*)d_in[15];
    const float* ln_g   = (const float*)d_in[16];
    const float* ln_b   = (const float*)d_in[17];
    const float* ro_w1  = (const float*)d_in[18];
    const float* ro_b1  = (const float*)d_in[19];
    const float* ro_w2  = (const float*)d_in[20];
    const float* ro_b2  = (const float*)d_in[21];
    const float* ro_w3  = (const float*)d_in[22];
    const float* ro_b3  = (const float*)d_in[23];
    float* out = (float*)d_out;

    float *px, *pPQ, *pH, *pA, *pgi, *pgh, *pdegf;
    int* pdeg;
    cudaGetSymbolAddress((void**)&px, g_x);
    cudaGetSymbolAddress((void**)&pPQ, g_PQ);
    cudaGetSymbolAddress((void**)&pH, g_Hagg);
    cudaGetSymbolAddress((void**)&pA, g_aggr);
    cudaGetSymbolAddress((void**)&pgi, g_gi);
    cudaGetSymbolAddress((void**)&pgh, g_gh);
    cudaGetSymbolAddress((void**)&pdegf, g_degf);
    cudaGetSymbolAddress((void**)&pdeg, g_deg);

    cudaMemsetAsync(pdeg, 0, N_NODES * sizeof(int));

    encoder_k<<<(N_NODES + 7) / 8, 256>>>(af, enc_w, enc_b, enc_g, enc_bb);
    deg_k<<<(N_EDGES + 255) / 256, 256>>>(ei);
    scan_k<<<1, 1024>>>();
    scatter_k<<<(N_EDGES + 255) / 256, 256>>>(ei);

    const int MB = (N_NODES + 127) / 128;  // 782
    for (int l = 0; l < N_LAYER; l++) {
        const float* w1   = msg_w1 + (size_t)l * 257 * 256;
        const float* b1   = msg_b1 + (size_t)l * 256;
        const float* w2   = msg_w2 + (size_t)l * 256 * 128;
        const float* b2   = msg_b2 + (size_t)l * 128;
        const float* wihl = wih + (size_t)l * 384 * 128;
        const float* whhl = whh + (size_t)l * 384 * 128;
        const float* bihl = bih + (size_t)l * 384;
        const float* bhhl = bhh + (size_t)l * 384;

        dim3 gPQ(MB, 4);
        sgemm_k<false><<<gPQ, 256>>>(px, w1, pPQ, N_NODES, 128, 256, 128, 256, 512,
                                     nullptr, nullptr, nullptr);
        sgemm_k<false><<<gPQ, 256>>>(px, w1 + 128 * 256, pPQ + 256, N_NODES, 128, 256,
                                     128, 256, 512, nullptr, nullptr, nullptr);

        edge_agg_k<<<(N_NODES * 32 + 255) / 256, 256>>>(ei, ea, w1 + 256 * 256, b1);

        dim3 gAG(MB, 2);
        sgemm_k<false><<<gAG, 256>>>(pH, w2, pA, N_NODES, 256, 128, 256, 128, 128,
                                     nullptr, pdegf, b2);

        dim3 gGR(MB, 6);
        sgemm_k<true><<<gGR, 256>>>(pA, wihl, pgi, N_NODES, 128, 384, 128, 128, 384,
                                    bihl, nullptr, nullptr);
        sgemm_k<true><<<gGR, 256>>>(px, whhl, pgh, N_NODES, 128, 384, 128, 128, 384,
                                    bhhl, nullptr, nullptr);

        gru_ln_k<<<(N_NODES * 32 + 255) / 256, 256>>>(ln_g + (size_t)l * 128,
                                                      ln_b + (size_t)l * 128);
    }

    init_pool_k<<<(N_GRAPH * HDIM + 255) / 256, 256>>>();
    cnt_k<<<(N_NODES + 255) / 256, 256>>>(batch);
    pool_k<<<(N_NODES * HDIM + 255) / 256, 256>>>(batch);
    readout_k<<<N_GRAPH, 128>>>(ro_w1, ro_b1, ro_w2, ro_b2, ro_w3, ro_b3, out);
}